// round 13
// baseline (speedup 1.0000x reference)
#include <cuda_runtime.h>
#include <math.h>

#define BB 16
#define NN 1024
#define FF 200
#define BN_ (BB*NN)          // 16384
#define C1 40
#define WO 35
#define KEFF 30
#define M4 560               // BB*WO
#define K4DIM 40960          // C1*NN
#define SPLIT 64
#define KSPL (K4DIM/SPLIT)   // 640
#define KC5 14
#define KC6 8
#define K2B_SPLIT 8
#define CGRP 8               // channels per k3 block

// ---------------- packed fp32x2 FMA (sm_103a) --------------------------------
__device__ __forceinline__ float2 ffma2(float2 a, float2 b, float2 c){
  unsigned long long ra = *reinterpret_cast<unsigned long long*>(&a);
  unsigned long long rb = *reinterpret_cast<unsigned long long*>(&b);
  unsigned long long rc = *reinterpret_cast<unsigned long long*>(&c);
  unsigned long long rd;
  asm("fma.rn.f32x2 %0, %1, %2, %3;" : "=l"(rd) : "l"(ra), "l"(rb), "l"(rc));
  return *reinterpret_cast<float2*>(&rd);
}

__device__ __forceinline__ float elu_fast(float s){
  return (s>0.f) ? s : (__expf(s) - 1.0f);
}

// ---------------- scratch ------------------------------------------------------
__device__ float g_h[BN_*FF];            // 13.1 MB
__device__ float g_as[NN];
__device__ float g_ad[NN];
__device__ float g_p[NN*NN];             // 4 MB normalized attention probs
__device__ float g_o2p[K2B_SPLIT*NN*FF]; // 6.6 MB attention GEMM partials
__device__ float g_y1[M4*K4DIM];         // 91.8 MB fp32 [(b*35+w)][c*1024+n]
__device__ float g_y2p[SPLIT*M4*40];
__device__ float g_y3[BB*1400];
__device__ float g_zp[KC5*BB*1024];      // FC1 split-K partials
__device__ float g_z2p[KC6*BB*1024];     // FC2 split-K partials

// ---------------- K1: h = X @ gat_W, fused attention scores -------------------
__global__ void k1_gemm(const float* __restrict__ x, const float* __restrict__ W,
                        const float* __restrict__ asw, const float* __restrict__ adw){
  __shared__ float xsT[8][68];
  __shared__ float ws[8][200];
  __shared__ float sAs[64], sAd[64];
  int row0 = blockIdx.x*64;
  int tid = threadIdx.x;          // 200
  int tr = tid & 7;
  int tc = tid >> 3;              // 0..24
  if (tid < 64){ sAs[tid]=0.f; sAd[tid]=0.f; }
  float2 acc[8][4];
  #pragma unroll
  for (int r=0;r<8;r++)
    #pragma unroll
    for (int p=0;p<4;p++) acc[r][p]=make_float2(0.f,0.f);

  float px[3], pw[8];
  #pragma unroll
  for (int l=0;l<3;l++){
    int idx = tid + l*200;
    if (idx<512){
      int kk = idx & 7, row = idx >> 3;
      px[l] = x[(row0+row)*200 + kk];
    }
  }
  #pragma unroll
  for (int l=0;l<8;l++){
    int idx = tid + l*200;
    int kk = idx/200, j = idx%200;
    pw[l] = W[kk*200 + j];
  }

  for (int t=0;t<25;t++){
    __syncthreads();
    #pragma unroll
    for (int l=0;l<3;l++){
      int idx = tid + l*200;
      if (idx<512){
        int kk = idx & 7, row = idx >> 3;
        xsT[kk][row] = px[l];
      }
    }
    #pragma unroll
    for (int l=0;l<8;l++){
      int idx = tid + l*200;
      int kk = idx/200, j = idx%200;
      ws[kk][j] = pw[l];
    }
    if (t<24){
      int k0 = (t+1)*8;
      #pragma unroll
      for (int l=0;l<3;l++){
        int idx = tid + l*200;
        if (idx<512){
          int kk = idx & 7, row = idx >> 3;
          px[l] = x[(row0+row)*200 + k0 + kk];
        }
      }
      #pragma unroll
      for (int l=0;l<8;l++){
        int idx = tid + l*200;
        int kk = idx/200, j = idx%200;
        pw[l] = W[(k0+kk)*200 + j];
      }
    }
    __syncthreads();
    #pragma unroll
    for (int kk=0;kk<8;kk++){
      float4 a0 = *reinterpret_cast<const float4*>(&xsT[kk][tr*4]);
      float4 a1 = *reinterpret_cast<const float4*>(&xsT[kk][32+tr*4]);
      float4 b0 = *reinterpret_cast<const float4*>(&ws[kk][tc*4]);
      float4 b1 = *reinterpret_cast<const float4*>(&ws[kk][100+tc*4]);
      float2 bp0 = make_float2(b0.x,b0.y), bp1 = make_float2(b0.z,b0.w);
      float2 bp2 = make_float2(b1.x,b1.y), bp3 = make_float2(b1.z,b1.w);
      float as[8] = {a0.x,a0.y,a0.z,a0.w,a1.x,a1.y,a1.z,a1.w};
      #pragma unroll
      for (int r=0;r<8;r++){
        float2 ar = make_float2(as[r],as[r]);
        acc[r][0]=ffma2(ar,bp0,acc[r][0]);
        acc[r][1]=ffma2(ar,bp1,acc[r][1]);
        acc[r][2]=ffma2(ar,bp2,acc[r][2]);
        acc[r][3]=ffma2(ar,bp3,acc[r][3]);
      }
    }
  }
  #pragma unroll
  for (int r=0;r<8;r++){
    int row = row0 + ((r<4) ? (tr*4+r) : (32+tr*4+(r-4)));
    float4 v0 = make_float4(acc[r][0].x,acc[r][0].y,acc[r][1].x,acc[r][1].y);
    float4 v1 = make_float4(acc[r][2].x,acc[r][2].y,acc[r][3].x,acc[r][3].y);
    *reinterpret_cast<float4*>(&g_h[row*200 + tc*4])       = v0;
    *reinterpret_cast<float4*>(&g_h[row*200 + 100 + tc*4]) = v1;
  }
  if (row0 < NN){
    float s0=asw[tc*4], s1=asw[tc*4+1], s2=asw[tc*4+2], s3=asw[tc*4+3];
    float s4=asw[100+tc*4], s5=asw[100+tc*4+1], s6=asw[100+tc*4+2], s7=asw[100+tc*4+3];
    float d0=adw[tc*4], d1=adw[tc*4+1], d2=adw[tc*4+2], d3=adw[tc*4+3];
    float d4=adw[100+tc*4], d5=adw[100+tc*4+1], d6=adw[100+tc*4+2], d7=adw[100+tc*4+3];
    #pragma unroll
    for (int r=0;r<8;r++){
      int rowl = (r<4) ? (tr*4+r) : (32+tr*4+(r-4));
      float ps = acc[r][0].x*s0 + acc[r][0].y*s1 + acc[r][1].x*s2 + acc[r][1].y*s3
               + acc[r][2].x*s4 + acc[r][2].y*s5 + acc[r][3].x*s6 + acc[r][3].y*s7;
      float pd = acc[r][0].x*d0 + acc[r][0].y*d1 + acc[r][1].x*d2 + acc[r][1].y*d3
               + acc[r][2].x*d4 + acc[r][2].y*d5 + acc[r][3].x*d6 + acc[r][3].y*d7;
      atomicAdd(&sAs[rowl], ps);
      atomicAdd(&sAd[rowl], pd);
    }
    __syncthreads();
    if (tid < 64){
      g_as[row0+tid] = sAs[tid];
      g_ad[row0+tid] = sAd[tid];
    }
  }
}

// ---------------- K2a: softmax rows -> normalized probs g_p -------------------
__global__ void k2a_softmax(){
  __shared__ float as_sh[1024];
  int tid = threadIdx.x;     // 256
  int lane = tid & 31, w = tid >> 5;
  int i = blockIdx.x*8 + w;
  for (int idx=tid; idx<1024; idx+=256) as_sh[idx]=g_as[idx];
  __syncthreads();
  float ad = g_ad[i];
  float v[32];
  float mx = -1e30f;
  #pragma unroll
  for (int t=0;t<32;t++){
    float s = as_sh[lane + 32*t] + ad;
    float l = s>0.f ? s : 0.2f*s;
    v[t]=l;
    mx=fmaxf(mx,l);
  }
  #pragma unroll
  for (int o=16;o>0;o>>=1) mx=fmaxf(mx,__shfl_xor_sync(0xffffffffu,mx,o));
  float sum=0.f;
  #pragma unroll
  for (int t=0;t<32;t++){ v[t]=__expf(v[t]-mx); sum+=v[t]; }
  #pragma unroll
  for (int o=16;o>0;o>>=1) sum+=__shfl_xor_sync(0xffffffffu,sum,o);
  float inv = 1.f/sum;
  #pragma unroll
  for (int t=0;t<32;t++) g_p[i*1024 + lane + 32*t] = v[t]*inv;
}

// ---------------- K2b: attention GEMM out = p @ h0, split-K 8 -----------------
__global__ void k2b_gemm(){
  __shared__ float psT[8][68];
  __shared__ float hs[8][200];
  int i0 = blockIdx.x*64;
  int ks = blockIdx.y;
  int j0 = ks*128;
  int tid = threadIdx.x;      // 200
  int tr = tid & 7;
  int tc = tid >> 3;
  float2 acc[8][4];
  #pragma unroll
  for (int r=0;r<8;r++)
    #pragma unroll
    for (int p=0;p<4;p++) acc[r][p]=make_float2(0.f,0.f);

  float pp[3], ph[8];
  #pragma unroll
  for (int l=0;l<3;l++){
    int idx = tid + l*200;
    if (idx<512){
      int kk = idx & 7, row = idx >> 3;
      pp[l] = g_p[(i0+row)*1024 + j0 + kk];
    }
  }
  #pragma unroll
  for (int l=0;l<8;l++){
    int idx = tid + l*200;
    int kk = idx/200, j = idx%200;
    ph[l] = g_h[(j0+kk)*200 + j];
  }

  for (int t=0;t<16;t++){
    __syncthreads();
    #pragma unroll
    for (int l=0;l<3;l++){
      int idx = tid + l*200;
      if (idx<512){
        int kk = idx & 7, row = idx >> 3;
        psT[kk][row] = pp[l];
      }
    }
    #pragma unroll
    for (int l=0;l<8;l++){
      int idx = tid + l*200;
      int kk = idx/200, j = idx%200;
      hs[kk][j] = ph[l];
    }
    if (t<15){
      int jj0 = j0 + (t+1)*8;
      #pragma unroll
      for (int l=0;l<3;l++){
        int idx = tid + l*200;
        if (idx<512){
          int kk = idx & 7, row = idx >> 3;
          pp[l] = g_p[(i0+row)*1024 + jj0 + kk];
        }
      }
      #pragma unroll
      for (int l=0;l<8;l++){
        int idx = tid + l*200;
        int kk = idx/200, j = idx%200;
        ph[l] = g_h[(jj0+kk)*200 + j];
      }
    }
    __syncthreads();
    #pragma unroll
    for (int kk=0;kk<8;kk++){
      float4 a0 = *reinterpret_cast<const float4*>(&psT[kk][tr*4]);
      float4 a1 = *reinterpret_cast<const float4*>(&psT[kk][32+tr*4]);
      float4 b0 = *reinterpret_cast<const float4*>(&hs[kk][tc*4]);
      float4 b1 = *reinterpret_cast<const float4*>(&hs[kk][100+tc*4]);
      float2 bp0 = make_float2(b0.x,b0.y), bp1 = make_float2(b0.z,b0.w);
      float2 bp2 = make_float2(b1.x,b1.y), bp3 = make_float2(b1.z,b1.w);
      float as[8] = {a0.x,a0.y,a0.z,a0.w,a1.x,a1.y,a1.z,a1.w};
      #pragma unroll
      for (int r=0;r<8;r++){
        float2 ar = make_float2(as[r],as[r]);
        acc[r][0]=ffma2(ar,bp0,acc[r][0]);
        acc[r][1]=ffma2(ar,bp1,acc[r][1]);
        acc[r][2]=ffma2(ar,bp2,acc[r][2]);
        acc[r][3]=ffma2(ar,bp3,acc[r][3]);
      }
    }
  }
  size_t obase = (size_t)ks*(NN*FF);
  #pragma unroll
  for (int r=0;r<8;r++){
    int i = i0 + ((r<4) ? (tr*4+r) : (32+tr*4+(r-4)));
    float4 v0 = make_float4(acc[r][0].x,acc[r][0].y,acc[r][1].x,acc[r][1].y);
    float4 v1 = make_float4(acc[r][2].x,acc[r][2].y,acc[r][3].x,acc[r][3].y);
    *reinterpret_cast<float4*>(&g_o2p[obase + i*200 + tc*4])       = v0;
    *reinterpret_cast<float4*>(&g_o2p[obase + i*200 + 100 + tc*4]) = v1;
  }
}

// ---------------- K3: residual + conv1 + pool + BN1 + fast ELU ----------------
// Channel-split: blockIdx.z picks 8 of 40 channels -> 2560 blocks.
// b==0 blocks reduce the attention partials inline.
__global__ void k3_conv(const float* __restrict__ x, const float* __restrict__ gat_b,
                        const float* __restrict__ cw, const float* __restrict__ cb,
                        const float* __restrict__ bg, const float* __restrict__ bbt,
                        const float* __restrict__ bm, const float* __restrict__ bv){
  __shared__ float2 xsT[200][16];
  __shared__ float wf[CGRP*KEFF];
  __shared__ float off[CGRP];
  int n0 = blockIdx.x*32;
  int b  = blockIdx.y;
  int c0 = blockIdx.z*CGRP;
  int tid = threadIdx.x;            // 112
  for (int idx=tid; idx<CGRP*KEFF; idx+=112){
    int cl = idx/KEFF, j = idx%KEFF;
    int c = c0 + cl;
    float s = bg[c]*rsqrtf(bv[c]+1e-5f);
    float a=0.f;
    int t0 = (j-25>0)? j-25 : 0;
    int t1 = (j<4)? j : 4;
    for (int t=t0;t<=t1;t++) a += cw[c*26 + (j-t)];
    wf[idx] = a*0.2f*s;
  }
  if (tid<CGRP){
    int c = c0 + tid;
    float s = bg[c]*rsqrtf(bv[c]+1e-5f);
    off[tid] = (cb[c]-bm[c])*s + bbt[c];
  }
  for (int idx=tid; idx<32*200; idx+=112){
    int row = idx/200, k = idx%200;
    float v;
    if (b==0){
      int offi = (n0+row)*200 + k;
      float s = x[offi] + gat_b[k];
      #pragma unroll
      for (int ks2=0;ks2<K2B_SPLIT;ks2++) s += g_o2p[ks2*(NN*FF) + offi];
      v = s;
    } else {
      int gi = (b*NN + n0 + row)*200 + k;
      v = x[gi] + g_h[gi] + gat_b[k];
    }
    ((float*)xsT)[(k*16 + (row>>1))*2 + (row&1)] = v;
  }
  __syncthreads();
  int np = tid & 15;
  int wg = tid >> 4;   // 0..6
  float2 xw[50];
  #pragma unroll
  for (int kk=0;kk<50;kk++) xw[kk]=xsT[wg*25+kk][np];
  #pragma unroll
  for (int cl=0;cl<CGRP;cl++){
    float oc = off[cl];
    float2 s0=make_float2(oc,oc), s1=s0, s2=s0, s3=s0, s4=s0;
    #pragma unroll
    for (int j=0;j<30;j++){
      float wv = wf[cl*30+j];
      float2 w2 = make_float2(wv,wv);
      s0 = ffma2(xw[j   ], w2, s0);
      s1 = ffma2(xw[j+5 ], w2, s1);
      s2 = ffma2(xw[j+10], w2, s2);
      s3 = ffma2(xw[j+15], w2, s3);
      s4 = ffma2(xw[j+20], w2, s4);
    }
    float2 ss[5] = {s0,s1,s2,s3,s4};
    int c = c0 + cl;
    #pragma unroll
    for (int i=0;i<5;i++){
      float2 r;
      r.x = elu_fast(ss[i].x);
      r.y = elu_fast(ss[i].y);
      int w = wg*5+i;
      *reinterpret_cast<float2*>(
        &g_y1[((size_t)(b*WO + w)*C1 + c)*NN + n0 + 2*np]) = r;
    }
  }
}

// ---------------- K4: conv2 GEMM (560x40, K=40960), split-K 64, prefetched ----
__global__ void k4_gemm(const float* __restrict__ W){
  __shared__ float As[64][33];
  __shared__ float2 Bs2[32][21];
  int m0 = blockIdx.x*64;
  int ks = blockIdx.y;
  int k0 = ks*KSPL;
  int tid = threadIdx.x;  // 160
  int tm = tid % 16;
  int to = tid / 16;      // 0..9
  float2 acc[4][2];
  #pragma unroll
  for (int i=0;i<4;i++){ acc[i][0]=make_float2(0.f,0.f); acc[i][1]=make_float2(0.f,0.f); }
  float ra[13], rb[8];
  #pragma unroll
  for (int l=0;l<13;l++){
    int idx = tid + l*160;
    if (idx<2048){
      int r = idx>>5, k = idx&31; int m = m0+r;
      ra[l] = (m<M4)? g_y1[(size_t)m*K4DIM + k0 + k] : 0.f;
    }
  }
  #pragma unroll
  for (int l=0;l<8;l++){
    int idx = tid + l*160;
    int o = idx>>5, k = idx&31;
    rb[l] = W[o*K4DIM + k0 + k];
  }
  for (int kc=0; kc<KSPL; kc+=32){
    __syncthreads();
    #pragma unroll
    for (int l=0;l<13;l++){
      int idx = tid + l*160;
      if (idx<2048){ int r = idx>>5, k = idx&31; As[r][k]=ra[l]; }
    }
    #pragma unroll
    for (int l=0;l<8;l++){
      int idx = tid + l*160;
      int o = idx>>5, k = idx&31;
      ((float*)Bs2)[(k*21 + (o>>1))*2 + (o&1)] = rb[l];
    }
    if (kc+32<KSPL){
      int kk = k0+kc+32;
      #pragma unroll
      for (int l=0;l<13;l++){
        int idx = tid + l*160;
        if (idx<2048){
          int r = idx>>5, k = idx&31; int m = m0+r;
          ra[l] = (m<M4)? g_y1[(size_t)m*K4DIM + kk + k] : 0.f;
        }
      }
      #pragma unroll
      for (int l=0;l<8;l++){
        int idx = tid + l*160;
        int o = idx>>5, k = idx&31;
        rb[l] = W[o*K4DIM + kk + k];
      }
    }
    __syncthreads();
    #pragma unroll
    for (int k=0;k<32;k++){
      float2 b0 = Bs2[k][to*2], b1 = Bs2[k][to*2+1];
      #pragma unroll
      for (int i=0;i<4;i++){
        float a = As[tm*4+i][k];
        float2 a2 = make_float2(a,a);
        acc[i][0] = ffma2(a2, b0, acc[i][0]);
        acc[i][1] = ffma2(a2, b1, acc[i][1]);
      }
    }
  }
  #pragma unroll
  for (int i=0;i<4;i++){
    int m = m0 + tm*4 + i;
    if (m < M4){
      float* dst = &g_y2p[(ks*M4 + m)*40 + to*4];
      dst[0]=acc[i][0].x; dst[1]=acc[i][0].y; dst[2]=acc[i][1].x; dst[3]=acc[i][1].y;
    }
  }
}

// ---------------- K4b: split-K reduce (parallel) + BN2 + ELU + projc ----------
__global__ void k4b_epi(const float* __restrict__ cb2, const float* __restrict__ g2,
                        const float* __restrict__ bb2, const float* __restrict__ m2,
                        const float* __restrict__ v2, const float* __restrict__ pw,
                        const float* __restrict__ pb){
  __shared__ float part[8][40];
  __shared__ float vsh[40];
  int row = blockIdx.x;
  int tid = threadIdx.x;  // 320
  {
    int o = tid%40, grp = tid/40;
    float a=0.f;
    #pragma unroll
    for (int s2=0;s2<8;s2++) a += g_y2p[((grp*8+s2)*M4+row)*40+o];
    part[grp][o]=a;
  }
  __syncthreads();
  if (tid<40){
    float acc = cb2[tid];
    #pragma unroll
    for (int g=0;g<8;g++) acc += part[g][tid];
    float sc = g2[tid]*rsqrtf(v2[tid]+1e-5f);
    float t = (acc - m2[tid])*sc + bb2[tid];
    vsh[tid] = (t>0.f)? t : expm1f(t);
  }
  __syncthreads();
  if (tid<40){
    float acc = pb[tid];
    #pragma unroll
    for (int o=0;o<40;o++) acc += vsh[o]*pw[tid*40+o];
    int b=row/WO, w=row%WO;
    g_y3[b*1400 + w*40 + tid] = acc;
  }
}

// ---------------- K5: FC1 partial GEMM, K split 14 -----------------------------
__global__ void k5_fc1(const float* __restrict__ W1){
  __shared__ float ys[16][100];
  int jb = blockIdx.x, kc = blockIdx.y;
  int tid = threadIdx.x;  // 128
  for (int idx=tid; idx<1600; idx+=128){
    int b = idx/100, ii = idx%100;
    ys[b][ii] = g_y3[b*1400 + kc*100 + ii];
  }
  __syncthreads();
  int j = jb*128 + tid;
  float acc[16];
  #pragma unroll
  for (int b=0;b<16;b++) acc[b]=0.f;
  #pragma unroll 10
  for (int ii=0; ii<100; ii++){
    float w = W1[(kc*100+ii)*1024 + j];
    #pragma unroll
    for (int b=0;b<16;b++) acc[b] += ys[b][ii]*w;
  }
  #pragma unroll
  for (int b=0;b<16;b++)
    g_zp[(kc*16+b)*1024 + j] = acc[b];
}

// ---------------- K6a: partial gelu(z)@W2, K split 8 (reduces zp inline) ------
__global__ void k6a_fc2(const float* __restrict__ W2, const float* __restrict__ b1){
  __shared__ float gs[16][128];
  int jb = blockIdx.x, kc = blockIdx.y;
  int tid = threadIdx.x;  // 128
  for (int idx=tid; idx<2048; idx+=128){
    int b = idx >> 7, ii = idx & 127;
    int j2 = kc*128 + ii;
    float zv = b1[j2];
    #pragma unroll
    for (int c5=0;c5<KC5;c5++) zv += g_zp[(c5*16+b)*1024 + j2];
    gs[b][ii] = 0.5f*zv*(1.f+erff(zv*0.7071067811865476f));
  }
  __syncthreads();
  int j = jb*128 + tid;
  float acc[16];
  #pragma unroll
  for (int b=0;b<16;b++) acc[b]=0.f;
  #pragma unroll 8
  for (int ii=0; ii<128; ii++){
    float w = W2[(kc*128+ii)*1024 + j];
    #pragma unroll
    for (int b=0;b<16;b++) acc[b] += gs[b][ii]*w;
  }
  #pragma unroll
  for (int b=0;b<16;b++)
    g_z2p[(kc*16+b)*1024 + j] = acc[b];
}

// ---------------- K6b: z (re-reduced) + partials + b2, LayerNorm ---------------
__global__ void k6b_ln(const float* __restrict__ b1, const float* __restrict__ b2,
                       const float* __restrict__ lng, const float* __restrict__ lnb,
                       float* __restrict__ out){
  __shared__ float red[32];
  __shared__ float sMu, sVar;
  int b = blockIdx.x, j = threadIdx.x;
  int lane=j&31, wid=j>>5;
  float zv = b1[j];
  #pragma unroll
  for (int c5=0;c5<KC5;c5++) zv += g_zp[(c5*16+b)*1024 + j];
  float acc = zv + b2[j];
  #pragma unroll
  for (int kc=0;kc<KC6;kc++) acc += g_z2p[(kc*16+b)*1024 + j];
  float z2 = acc;
  float s=z2;
  #pragma unroll
  for (int o=16;o>0;o>>=1) s+=__shfl_xor_sync(0xffffffffu,s,o);
  if (lane==0) red[wid]=s;
  __syncthreads();
  if (wid==0){
    float t=red[lane];
    #pragma unroll
    for (int o=16;o>0;o>>=1) t+=__shfl_xor_sync(0xffffffffu,t,o);
    if (lane==0) sMu = t*(1.f/1024.f);
  }
  __syncthreads();
  float mu=sMu;
  float d=z2-mu;
  s=d*d;
  #pragma unroll
  for (int o=16;o>0;o>>=1) s+=__shfl_xor_sync(0xffffffffu,s,o);
  if (lane==0) red[wid]=s;
  __syncthreads();
  if (wid==0){
    float t=red[lane];
    #pragma unroll
    for (int o=16;o>0;o>>=1) t+=__shfl_xor_sync(0xffffffffu,t,o);
    if (lane==0) sVar = t*(1.f/1024.f);
  }
  __syncthreads();
  out[b*1024+j] = d*rsqrtf(sVar+1e-5f)*lng[j] + lnb[j];
}

// ---------------- launch --------------------------------------------------------
extern "C" void kernel_launch(void* const* d_in, const int* in_sizes, int n_in,
                              void* d_out, int out_size) {
  const float* x       = (const float*)d_in[0];
  const float* gat_W   = (const float*)d_in[1];
  const float* att_src = (const float*)d_in[2];
  const float* att_dst = (const float*)d_in[3];
  const float* gat_b   = (const float*)d_in[4];
  const float* conv1_w = (const float*)d_in[5];
  const float* conv1_b = (const float*)d_in[6];
  const float* bn1_g   = (const float*)d_in[7];
  const float* bn1_b   = (const float*)d_in[8];
  const float* bn1_m   = (const float*)d_in[9];
  const float* bn1_v   = (const float*)d_in[10];
  const float* conv2_w = (const float*)d_in[11];
  const float* conv2_b = (const float*)d_in[12];
  const float* bn2_g   = (const float*)d_in[13];
  const float* bn2_b   = (const float*)d_in[14];
  const float* bn2_m   = (const float*)d_in[15];
  const float* bn2_v   = (const float*)d_in[16];
  const float* projc_w = (const float*)d_in[17];
  const float* projc_b = (const float*)d_in[18];
  const float* W1      = (const float*)d_in[19];
  const float* b1      = (const float*)d_in[20];
  const float* W2      = (const float*)d_in[21];
  const float* b2      = (const float*)d_in[22];
  const float* ln_g    = (const float*)d_in[23];
  const float* ln_b    = (const float*)d_in[24];
  float* out = (float*)d_out;

  k1_gemm<<<BN_/64, 200>>>(x, gat_W, att_src, att_dst);
  k2a_softmax<<<NN/8, 256>>>();
  k2b_gemm<<<dim3(16, K2B_SPLIT), 200>>>();
  k3_conv<<<dim3(NN/32, BB, C1/CGRP), 112>>>(x, gat_b, conv1_w, conv1_b,
                                             bn1_g, bn1_b, bn1_m, bn1_v);
  k4_gemm<<<dim3(9, SPLIT), 160>>>(conv2_w);
  k4b_epi<<<M4, 320>>>(conv2_b, bn2_g, bn2_b, bn2_m, bn2_v, projc_w, projc_b);
  k5_fc1<<<dim3(8, KC5), 128>>>(W1);
  k6a_fc2<<<dim3(8, KC6), 128>>>(W2, b1);
  k6b_ln<<<BB, 1024>>>(b1, b2, ln_g, ln_b, out);
}

// round 14
// speedup vs baseline: 1.3973x; 1.3973x over previous
#include <cuda_runtime.h>
#include <math.h>

#define BB 16
#define NN 1024
#define FF 200
#define BN_ (BB*NN)          // 16384
#define C1 40
#define WO 35
#define KEFF 30
#define M4 560               // BB*WO
#define K4DIM 40960          // C1*NN
#define SPLIT 64
#define KSPL (K4DIM/SPLIT)   // 640
#define KC5 14
#define KC6 8
#define K2_SMEM ((1024*8 + 2*32*200)*4)   // 83968 bytes

// ---------------- packed fp32x2 FMA (sm_103a) --------------------------------
__device__ __forceinline__ float2 ffma2(float2 a, float2 b, float2 c){
  unsigned long long ra = *reinterpret_cast<unsigned long long*>(&a);
  unsigned long long rb = *reinterpret_cast<unsigned long long*>(&b);
  unsigned long long rc = *reinterpret_cast<unsigned long long*>(&c);
  unsigned long long rd;
  asm("fma.rn.f32x2 %0, %1, %2, %3;" : "=l"(rd) : "l"(ra), "l"(rb), "l"(rc));
  return *reinterpret_cast<float2*>(&rd);
}

__device__ __forceinline__ float elu_fast(float s){
  return (s>0.f) ? s : (__expf(s) - 1.0f);
}

// ---------------- scratch ------------------------------------------------------
__device__ float g_h[BN_*FF];          // 13.1 MB
__device__ float g_as[NN];
__device__ float g_ad[NN];
__device__ float g_xh[NN*FF];          // graph-0 rows only (k2 output)
__device__ float g_y1[M4*K4DIM];       // 91.8 MB fp32 [(b*35+w)][c*1024+n]
__device__ float g_y2p[SPLIT*M4*40];
__device__ float g_y3[BB*1400];
__device__ float g_zp[KC5*BB*1024];    // FC1 split-K partials
__device__ float g_z2p[KC6*BB*1024];   // FC2 split-K partials

// ---------------- K1: h = X @ gat_W, fused attention scores -------------------
__global__ void k1_gemm(const float* __restrict__ x, const float* __restrict__ W,
                        const float* __restrict__ asw, const float* __restrict__ adw){
  __shared__ float xsT[8][68];
  __shared__ float ws[8][200];
  __shared__ float sAs[64], sAd[64];
  int row0 = blockIdx.x*64;
  int tid = threadIdx.x;          // 200
  int tr = tid & 7;
  int tc = tid >> 3;              // 0..24
  if (tid < 64){ sAs[tid]=0.f; sAd[tid]=0.f; }
  float2 acc[8][4];
  #pragma unroll
  for (int r=0;r<8;r++)
    #pragma unroll
    for (int p=0;p<4;p++) acc[r][p]=make_float2(0.f,0.f);

  float px[3], pw[8];
  #pragma unroll
  for (int l=0;l<3;l++){
    int idx = tid + l*200;
    if (idx<512){
      int kk = idx & 7, row = idx >> 3;
      px[l] = x[(row0+row)*200 + kk];
    }
  }
  #pragma unroll
  for (int l=0;l<8;l++){
    int idx = tid + l*200;
    int kk = idx/200, j = idx%200;
    pw[l] = W[kk*200 + j];
  }

  for (int t=0;t<25;t++){
    __syncthreads();
    #pragma unroll
    for (int l=0;l<3;l++){
      int idx = tid + l*200;
      if (idx<512){
        int kk = idx & 7, row = idx >> 3;
        xsT[kk][row] = px[l];
      }
    }
    #pragma unroll
    for (int l=0;l<8;l++){
      int idx = tid + l*200;
      int kk = idx/200, j = idx%200;
      ws[kk][j] = pw[l];
    }
    if (t<24){
      int k0 = (t+1)*8;
      #pragma unroll
      for (int l=0;l<3;l++){
        int idx = tid + l*200;
        if (idx<512){
          int kk = idx & 7, row = idx >> 3;
          px[l] = x[(row0+row)*200 + k0 + kk];
        }
      }
      #pragma unroll
      for (int l=0;l<8;l++){
        int idx = tid + l*200;
        int kk = idx/200, j = idx%200;
        pw[l] = W[(k0+kk)*200 + j];
      }
    }
    __syncthreads();
    #pragma unroll
    for (int kk=0;kk<8;kk++){
      float4 a0 = *reinterpret_cast<const float4*>(&xsT[kk][tr*4]);
      float4 a1 = *reinterpret_cast<const float4*>(&xsT[kk][32+tr*4]);
      float4 b0 = *reinterpret_cast<const float4*>(&ws[kk][tc*4]);
      float4 b1 = *reinterpret_cast<const float4*>(&ws[kk][100+tc*4]);
      float2 bp0 = make_float2(b0.x,b0.y), bp1 = make_float2(b0.z,b0.w);
      float2 bp2 = make_float2(b1.x,b1.y), bp3 = make_float2(b1.z,b1.w);
      float as[8] = {a0.x,a0.y,a0.z,a0.w,a1.x,a1.y,a1.z,a1.w};
      #pragma unroll
      for (int r=0;r<8;r++){
        float2 ar = make_float2(as[r],as[r]);
        acc[r][0]=ffma2(ar,bp0,acc[r][0]);
        acc[r][1]=ffma2(ar,bp1,acc[r][1]);
        acc[r][2]=ffma2(ar,bp2,acc[r][2]);
        acc[r][3]=ffma2(ar,bp3,acc[r][3]);
      }
    }
  }
  #pragma unroll
  for (int r=0;r<8;r++){
    int row = row0 + ((r<4) ? (tr*4+r) : (32+tr*4+(r-4)));
    float4 v0 = make_float4(acc[r][0].x,acc[r][0].y,acc[r][1].x,acc[r][1].y);
    float4 v1 = make_float4(acc[r][2].x,acc[r][2].y,acc[r][3].x,acc[r][3].y);
    *reinterpret_cast<float4*>(&g_h[row*200 + tc*4])       = v0;
    *reinterpret_cast<float4*>(&g_h[row*200 + 100 + tc*4]) = v1;
  }
  if (row0 < NN){
    float s0=asw[tc*4], s1=asw[tc*4+1], s2=asw[tc*4+2], s3=asw[tc*4+3];
    float s4=asw[100+tc*4], s5=asw[100+tc*4+1], s6=asw[100+tc*4+2], s7=asw[100+tc*4+3];
    float d0=adw[tc*4], d1=adw[tc*4+1], d2=adw[tc*4+2], d3=adw[tc*4+3];
    float d4=adw[100+tc*4], d5=adw[100+tc*4+1], d6=adw[100+tc*4+2], d7=adw[100+tc*4+3];
    #pragma unroll
    for (int r=0;r<8;r++){
      int rowl = (r<4) ? (tr*4+r) : (32+tr*4+(r-4));
      float ps = acc[r][0].x*s0 + acc[r][0].y*s1 + acc[r][1].x*s2 + acc[r][1].y*s3
               + acc[r][2].x*s4 + acc[r][2].y*s5 + acc[r][3].x*s6 + acc[r][3].y*s7;
      float pd = acc[r][0].x*d0 + acc[r][0].y*d1 + acc[r][1].x*d2 + acc[r][1].y*d3
               + acc[r][2].x*d4 + acc[r][2].y*d5 + acc[r][3].x*d6 + acc[r][3].y*d7;
      atomicAdd(&sAs[rowl], ps);
      atomicAdd(&sAd[rowl], pd);
    }
    __syncthreads();
    if (tid < 64){
      g_as[row0+tid] = sAs[tid];
      g_ad[row0+tid] = sAd[tid];
    }
  }
}

// ---------------- K2: dense GAT attention (graph 0), double-buffered ----------
__global__ void k2_attn(const float* __restrict__ x, const float* __restrict__ gat_b){
  extern __shared__ float sm[];
  float* pT  = sm;                 // [1024][8]
  float* hs0 = sm + 8192;          // 32x200
  float* hs1 = sm + 8192 + 6400;
  __shared__ float rowsum[8];
  int i0 = blockIdx.x*8;
  int tid = threadIdx.x;           // 256
  int lane = tid&31, w = tid>>5;
  {
    float ad = g_ad[i0+w];
    float mx = -1e30f;
    for (int jj=lane; jj<1024; jj+=32){
      float v = g_as[jj]+ad;
      float l = v>0.f? v : 0.2f*v;
      pT[jj*8+w]=l;
      mx=fmaxf(mx,l);
    }
    #pragma unroll
    for (int o=16;o>0;o>>=1) mx=fmaxf(mx,__shfl_xor_sync(0xffffffffu,mx,o));
    float sum=0.f;
    for (int jj=lane; jj<1024; jj+=32){
      float e=__expf(pT[jj*8+w]-mx);
      pT[jj*8+w]=e;
      sum+=e;
    }
    #pragma unroll
    for (int o=16;o>0;o>>=1) sum+=__shfl_xor_sync(0xffffffffu,sum,o);
    if (lane==0) rowsum[w]=sum;
  }
  __syncthreads();
  float2 acc2[4];
  #pragma unroll
  for (int p=0;p<4;p++) acc2[p]=make_float2(0.f,0.f);
  {
    const float4* src = (const float4*)g_h;
    float4* dst = (float4*)hs0;
    #pragma unroll
    for (int l=0;l<7;l++){ int idx = tid + l*256; if (idx<1600) dst[idx]=src[idx]; }
  }
  __syncthreads();
  for (int t=0;t<32;t++){
    float4 pf[7];
    const float* hb = (t&1)? hs1 : hs0;
    float* hn = (t&1)? hs0 : hs1;
    if (t<31){
      const float4* src = (const float4*)(g_h + (t+1)*6400);
      #pragma unroll
      for (int l=0;l<7;l++){ int idx = tid + l*256; if (idx<1600) pf[l]=src[idx]; }
    }
    if (tid<200){
      int j0 = t*32;
      #pragma unroll 8
      for (int jj=0;jj<32;jj++){
        float hv = hb[jj*200+tid];
        float2 h2 = make_float2(hv,hv);
        const float2* pp = (const float2*)(pT + (size_t)(j0+jj)*8);
        acc2[0]=ffma2(h2,pp[0],acc2[0]);
        acc2[1]=ffma2(h2,pp[1],acc2[1]);
        acc2[2]=ffma2(h2,pp[2],acc2[2]);
        acc2[3]=ffma2(h2,pp[3],acc2[3]);
      }
    }
    if (t<31){
      float4* dst=(float4*)hn;
      #pragma unroll
      for (int l=0;l<7;l++){ int idx = tid + l*256; if (idx<1600) dst[idx]=pf[l]; }
    }
    __syncthreads();
  }
  if (tid<200){
    float gb = gat_b[tid];
    #pragma unroll
    for (int p=0;p<4;p++){
      int i = i0+2*p;
      g_xh[i*200+tid]     = x[i*200+tid]     + acc2[p].x/rowsum[2*p]   + gb;
      g_xh[(i+1)*200+tid] = x[(i+1)*200+tid] + acc2[p].y/rowsum[2*p+1] + gb;
    }
  }
}

// ---------------- K3: residual + conv1 + pool + BN1 + fast ELU ----------------
__global__ void k3_conv(const float* __restrict__ x, const float* __restrict__ gat_b,
                        const float* __restrict__ cw, const float* __restrict__ cb,
                        const float* __restrict__ bg, const float* __restrict__ bbt,
                        const float* __restrict__ bm, const float* __restrict__ bv){
  __shared__ float2 xsT[200][16];
  __shared__ float wf[C1*KEFF];
  __shared__ float off[C1];
  int n0 = blockIdx.x*32;
  int b  = blockIdx.y;
  int tid = threadIdx.x;            // 112
  for (int idx=tid; idx<C1*KEFF; idx+=112){
    int c = idx/KEFF, j = idx%KEFF;
    float s = bg[c]*rsqrtf(bv[c]+1e-5f);
    float a=0.f;
    int t0 = (j-25>0)? j-25 : 0;
    int t1 = (j<4)? j : 4;
    for (int t=t0;t<=t1;t++) a += cw[c*26 + (j-t)];
    wf[idx] = a*0.2f*s;
  }
  if (tid<C1){
    float s = bg[tid]*rsqrtf(bv[tid]+1e-5f);
    off[tid] = (cb[tid]-bm[tid])*s + bbt[tid];
  }
  for (int idx=tid; idx<32*200; idx+=112){
    int row = idx/200, k = idx%200;
    float v;
    if (b==0) v = g_xh[(n0+row)*200 + k];
    else {
      int gi = (b*NN + n0 + row)*200 + k;
      v = x[gi] + g_h[gi] + gat_b[k];
    }
    ((float*)xsT)[(k*16 + (row>>1))*2 + (row&1)] = v;
  }
  __syncthreads();
  int np = tid & 15;
  int wg = tid >> 4;   // 0..6
  float2 xw[50];
  #pragma unroll
  for (int kk=0;kk<50;kk++) xw[kk]=xsT[wg*25+kk][np];
  for (int c=0;c<C1;c++){
    float oc = off[c];
    float2 s0=make_float2(oc,oc), s1=s0, s2=s0, s3=s0, s4=s0;
    #pragma unroll
    for (int j=0;j<30;j++){
      float wv = wf[c*30+j];
      float2 w2 = make_float2(wv,wv);
      s0 = ffma2(xw[j   ], w2, s0);
      s1 = ffma2(xw[j+5 ], w2, s1);
      s2 = ffma2(xw[j+10], w2, s2);
      s3 = ffma2(xw[j+15], w2, s3);
      s4 = ffma2(xw[j+20], w2, s4);
    }
    float2 ss[5] = {s0,s1,s2,s3,s4};
    #pragma unroll
    for (int i=0;i<5;i++){
      float2 r;
      r.x = elu_fast(ss[i].x);
      r.y = elu_fast(ss[i].y);
      int w = wg*5+i;
      *reinterpret_cast<float2*>(
        &g_y1[((size_t)(b*WO + w)*C1 + c)*NN + n0 + 2*np]) = r;
    }
  }
}

// ---------------- K4: conv2 GEMM (560x40, K=40960), split-K 64, prefetched ----
__global__ void k4_gemm(const float* __restrict__ W){
  __shared__ float As[64][33];
  __shared__ float2 Bs2[32][21];
  int m0 = blockIdx.x*64;
  int ks = blockIdx.y;
  int k0 = ks*KSPL;
  int tid = threadIdx.x;  // 160
  int tm = tid % 16;
  int to = tid / 16;      // 0..9
  float2 acc[4][2];
  #pragma unroll
  for (int i=0;i<4;i++){ acc[i][0]=make_float2(0.f,0.f); acc[i][1]=make_float2(0.f,0.f); }
  float ra[13], rb[8];
  #pragma unroll
  for (int l=0;l<13;l++){
    int idx = tid + l*160;
    if (idx<2048){
      int r = idx>>5, k = idx&31; int m = m0+r;
      ra[l] = (m<M4)? g_y1[(size_t)m*K4DIM + k0 + k] : 0.f;
    }
  }
  #pragma unroll
  for (int l=0;l<8;l++){
    int idx = tid + l*160;
    int o = idx>>5, k = idx&31;
    rb[l] = W[o*K4DIM + k0 + k];
  }
  for (int kc=0; kc<KSPL; kc+=32){
    __syncthreads();
    #pragma unroll
    for (int l=0;l<13;l++){
      int idx = tid + l*160;
      if (idx<2048){ int r = idx>>5, k = idx&31; As[r][k]=ra[l]; }
    }
    #pragma unroll
    for (int l=0;l<8;l++){
      int idx = tid + l*160;
      int o = idx>>5, k = idx&31;
      ((float*)Bs2)[(k*21 + (o>>1))*2 + (o&1)] = rb[l];
    }
    if (kc+32<KSPL){
      int kk = k0+kc+32;
      #pragma unroll
      for (int l=0;l<13;l++){
        int idx = tid + l*160;
        if (idx<2048){
          int r = idx>>5, k = idx&31; int m = m0+r;
          ra[l] = (m<M4)? g_y1[(size_t)m*K4DIM + kk + k] : 0.f;
        }
      }
      #pragma unroll
      for (int l=0;l<8;l++){
        int idx = tid + l*160;
        int o = idx>>5, k = idx&31;
        rb[l] = W[o*K4DIM + kk + k];
      }
    }
    __syncthreads();
    #pragma unroll
    for (int k=0;k<32;k++){
      float2 b0 = Bs2[k][to*2], b1 = Bs2[k][to*2+1];
      #pragma unroll
      for (int i=0;i<4;i++){
        float a = As[tm*4+i][k];
        float2 a2 = make_float2(a,a);
        acc[i][0] = ffma2(a2, b0, acc[i][0]);
        acc[i][1] = ffma2(a2, b1, acc[i][1]);
      }
    }
  }
  #pragma unroll
  for (int i=0;i<4;i++){
    int m = m0 + tm*4 + i;
    if (m < M4){
      float* dst = &g_y2p[(ks*M4 + m)*40 + to*4];
      dst[0]=acc[i][0].x; dst[1]=acc[i][0].y; dst[2]=acc[i][1].x; dst[3]=acc[i][1].y;
    }
  }
}

// ---------------- K4b: split-K reduce (parallel) + BN2 + ELU + projc ----------
__global__ void k4b_epi(const float* __restrict__ cb2, const float* __restrict__ g2,
                        const float* __restrict__ bb2, const float* __restrict__ m2,
                        const float* __restrict__ v2, const float* __restrict__ pw,
                        const float* __restrict__ pb){
  __shared__ float part[8][40];
  __shared__ float vsh[40];
  int row = blockIdx.x;
  int tid = threadIdx.x;  // 320
  {
    int o = tid%40, grp = tid/40;
    float a=0.f;
    #pragma unroll
    for (int s2=0;s2<8;s2++) a += g_y2p[((grp*8+s2)*M4+row)*40+o];
    part[grp][o]=a;
  }
  __syncthreads();
  if (tid<40){
    float acc = cb2[tid];
    #pragma unroll
    for (int g=0;g<8;g++) acc += part[g][tid];
    float sc = g2[tid]*rsqrtf(v2[tid]+1e-5f);
    float t = (acc - m2[tid])*sc + bb2[tid];
    vsh[tid] = elu_fast(t);
  }
  __syncthreads();
  if (tid<40){
    float acc = pb[tid];
    #pragma unroll
    for (int o=0;o<40;o++) acc += vsh[o]*pw[tid*40+o];
    int b=row/WO, w=row%WO;
    g_y3[b*1400 + w*40 + tid] = acc;
  }
}

// ---------------- K5: FC1 partial GEMM, K split 14 -----------------------------
__global__ void k5_fc1(const float* __restrict__ W1){
  __shared__ float ys[16][100];
  int jb = blockIdx.x, kc = blockIdx.y;
  int tid = threadIdx.x;  // 128
  for (int idx=tid; idx<1600; idx+=128){
    int b = idx/100, ii = idx%100;
    ys[b][ii] = g_y3[b*1400 + kc*100 + ii];
  }
  __syncthreads();
  int j = jb*128 + tid;
  float acc[16];
  #pragma unroll
  for (int b=0;b<16;b++) acc[b]=0.f;
  #pragma unroll 10
  for (int ii=0; ii<100; ii++){
    float w = W1[(kc*100+ii)*1024 + j];
    #pragma unroll
    for (int b=0;b<16;b++) acc[b] += ys[b][ii]*w;
  }
  #pragma unroll
  for (int b=0;b<16;b++)
    g_zp[(kc*16+b)*1024 + j] = acc[b];
}

// ---------------- K6a: partial gelu(z)@W2, K split 8 (reduces zp inline) ------
__global__ void k6a_fc2(const float* __restrict__ W2, const float* __restrict__ b1){
  __shared__ float gs[16][128];
  int jb = blockIdx.x, kc = blockIdx.y;
  int tid = threadIdx.x;  // 128
  for (int idx=tid; idx<2048; idx+=128){
    int b = idx >> 7, ii = idx & 127;
    int j2 = kc*128 + ii;
    float zv = b1[j2];
    #pragma unroll
    for (int c5=0;c5<KC5;c5++) zv += g_zp[(c5*16+b)*1024 + j2];
    gs[b][ii] = 0.5f*zv*(1.f+erff(zv*0.7071067811865476f));
  }
  __syncthreads();
  int j = jb*128 + tid;
  float acc[16];
  #pragma unroll
  for (int b=0;b<16;b++) acc[b]=0.f;
  #pragma unroll 8
  for (int ii=0; ii<128; ii++){
    float w = W2[(kc*128+ii)*1024 + j];
    #pragma unroll
    for (int b=0;b<16;b++) acc[b] += gs[b][ii]*w;
  }
  #pragma unroll
  for (int b=0;b<16;b++)
    g_z2p[(kc*16+b)*1024 + j] = acc[b];
}

// ---------------- K6b: z (re-reduced) + partials + b2, LayerNorm ---------------
__global__ void k6b_ln(const float* __restrict__ b1, const float* __restrict__ b2,
                       const float* __restrict__ lng, const float* __restrict__ lnb,
                       float* __restrict__ out){
  __shared__ float red[32];
  __shared__ float sMu, sVar;
  int b = blockIdx.x, j = threadIdx.x;
  int lane=j&31, wid=j>>5;
  float zv = b1[j];
  #pragma unroll
  for (int c5=0;c5<KC5;c5++) zv += g_zp[(c5*16+b)*1024 + j];
  float acc = zv + b2[j];
  #pragma unroll
  for (int kc=0;kc<KC6;kc++) acc += g_z2p[(kc*16+b)*1024 + j];
  float z2 = acc;
  float s=z2;
  #pragma unroll
  for (int o=16;o>0;o>>=1) s+=__shfl_xor_sync(0xffffffffu,s,o);
  if (lane==0) red[wid]=s;
  __syncthreads();
  if (wid==0){
    float t=red[lane];
    #pragma unroll
    for (int o=16;o>0;o>>=1) t+=__shfl_xor_sync(0xffffffffu,t,o);
    if (lane==0) sMu = t*(1.f/1024.f);
  }
  __syncthreads();
  float mu=sMu;
  float d=z2-mu;
  s=d*d;
  #pragma unroll
  for (int o=16;o>0;o>>=1) s+=__shfl_xor_sync(0xffffffffu,s,o);
  if (lane==0) red[wid]=s;
  __syncthreads();
  if (wid==0){
    float t=red[lane];
    #pragma unroll
    for (int o=16;o>0;o>>=1) t+=__shfl_xor_sync(0xffffffffu,t,o);
    if (lane==0) sVar = t*(1.f/1024.f);
  }
  __syncthreads();
  out[b*1024+j] = d*rsqrtf(sVar+1e-5f)*lng[j] + lnb[j];
}

// ---------------- launch --------------------------------------------------------
extern "C" void kernel_launch(void* const* d_in, const int* in_sizes, int n_in,
                              void* d_out, int out_size) {
  const float* x       = (const float*)d_in[0];
  const float* gat_W   = (const float*)d_in[1];
  const float* att_src = (const float*)d_in[2];
  const float* att_dst = (const float*)d_in[3];
  const float* gat_b   = (const float*)d_in[4];
  const float* conv1_w = (const float*)d_in[5];
  const float* conv1_b = (const float*)d_in[6];
  const float* bn1_g   = (const float*)d_in[7];
  const float* bn1_b   = (const float*)d_in[8];
  const float* bn1_m   = (const float*)d_in[9];
  const float* bn1_v   = (const float*)d_in[10];
  const float* conv2_w = (const float*)d_in[11];
  const float* conv2_b = (const float*)d_in[12];
  const float* bn2_g   = (const float*)d_in[13];
  const float* bn2_b   = (const float*)d_in[14];
  const float* bn2_m   = (const float*)d_in[15];
  const float* bn2_v   = (const float*)d_in[16];
  const float* projc_w = (const float*)d_in[17];
  const float* projc_b = (const float*)d_in[18];
  const float* W1      = (const float*)d_in[19];
  const float* b1      = (const float*)d_in[20];
  const float* W2      = (const float*)d_in[21];
  const float* b2      = (const float*)d_in[22];
  const float* ln_g    = (const float*)d_in[23];
  const float* ln_b    = (const float*)d_in[24];
  float* out = (float*)d_out;

  cudaFuncSetAttribute(k2_attn, cudaFuncAttributeMaxDynamicSharedMemorySize, K2_SMEM);

  k1_gemm<<<BN_/64, 200>>>(x, gat_W, att_src, att_dst);
  k2_attn<<<NN/8, 256, K2_SMEM>>>(x, gat_b);
  k3_conv<<<dim3(NN/32, BB), 112>>>(x, gat_b, conv1_w, conv1_b,
                                    bn1_g, bn1_b, bn1_m, bn1_v);
  k4_gemm<<<dim3(9, SPLIT), 160>>>(conv2_w);
  k4b_epi<<<M4, 320>>>(conv2_b, bn2_g, bn2_b, bn2_m, bn2_v, projc_w, projc_b);
  k5_fc1<<<dim3(8, KC5), 128>>>(W1);
  k6a_fc2<<<dim3(8, KC6), 128>>>(W2, b1);
  k6b_ln<<<BB, 1024>>>(b1, b2, ln_g, ln_b, out);
}